// round 1
// baseline (speedup 1.0000x reference)
#include <cuda_runtime.h>

#define NN 10000
#define NE 320000
#define HD 64
#define TIL 64
#define STR 68
#define NLAYERS 4

// ---------------- scratch state (allocation-free) ----------------
__device__ __align__(16) float g_h[NN * HD];
__device__ __align__(16) float g_agg[NN * HD];
__device__ float g_x[NN * 3];
__device__ float g_v[NN * 3];
__device__ float g_iv[NN * 3];
__device__ float g_acc3[NN * 3];
__device__ float g_cnt[NN];
__device__ int g_edge64;

__device__ __forceinline__ float silu_f(float x) {
    // x * sigmoid(x) = x / (1 + e^-x); MUFU-based, ~2^-21 rel err
    return __fdividef(x, 1.0f + __expf(-x));
}

__device__ __forceinline__ int edge_idx(const void* edges, long long i) {
    if (g_edge64) return (int)((const long long*)edges)[i];
    return ((const int*)edges)[i];
}

// ---------------- dtype detection for edges ----------------
__global__ void k_detect(const void* edges) {
    // If edges are int64 (values < 2^31), every odd int32 word is 0.
    const int* p = (const int*)edges;
    int is64 = 1;
    for (int i = 1; i < 64; i += 2)
        if (p[i] != 0) is64 = 0;
    g_edge64 = is64;
}

// ---------------- init: embedding, state copy, zero scratch ----------------
__global__ void k_init(const float* __restrict__ his, const float* __restrict__ loc,
                       const float* __restrict__ vel, const float* __restrict__ emb_w,
                       const float* __restrict__ emb_b) {
    int idx = blockIdx.x * blockDim.x + threadIdx.x;
    if (idx < NN * HD) {
        int n = idx >> 6, j = idx & 63;
        float a = emb_b[j];
#pragma unroll
        for (int i = 0; i < 4; i++) a = fmaf(his[n * 4 + i], emb_w[i * 64 + j], a);
        g_h[idx] = a;
        g_agg[idx] = 0.f;
    }
    if (idx < NN * 3) {
        g_x[idx] = loc[idx];
        g_v[idx] = vel[idx];
        g_acc3[idx] = 0.f;
    }
    if (idx < NN) {
        float vx = vel[idx * 3], vy = vel[idx * 3 + 1], vz = vel[idx * 3 + 2];
        float inv = 1.0f / (sqrtf(vx * vx + vy * vy + vz * vz) + 1e-8f);
        g_iv[idx * 3] = vx * inv;
        g_iv[idx * 3 + 1] = vy * inv;
        g_iv[idx * 3 + 2] = vz * inv;
        g_cnt[idx] = 0.f;
    }
}

#define FMA16(ACC, A, B)                                                     \
    do {                                                                     \
        ACC[0][0] = fmaf(A.x, B.x, ACC[0][0]);                               \
        ACC[0][1] = fmaf(A.x, B.y, ACC[0][1]);                               \
        ACC[0][2] = fmaf(A.x, B.z, ACC[0][2]);                               \
        ACC[0][3] = fmaf(A.x, B.w, ACC[0][3]);                               \
        ACC[1][0] = fmaf(A.y, B.x, ACC[1][0]);                               \
        ACC[1][1] = fmaf(A.y, B.y, ACC[1][1]);                               \
        ACC[1][2] = fmaf(A.y, B.z, ACC[1][2]);                               \
        ACC[1][3] = fmaf(A.y, B.w, ACC[1][3]);                               \
        ACC[2][0] = fmaf(A.z, B.x, ACC[2][0]);                               \
        ACC[2][1] = fmaf(A.z, B.y, ACC[2][1]);                               \
        ACC[2][2] = fmaf(A.z, B.z, ACC[2][2]);                               \
        ACC[2][3] = fmaf(A.z, B.w, ACC[2][3]);                               \
        ACC[3][0] = fmaf(A.w, B.x, ACC[3][0]);                               \
        ACC[3][1] = fmaf(A.w, B.y, ACC[3][1]);                               \
        ACC[3][2] = fmaf(A.w, B.z, ACC[3][2]);                               \
        ACC[3][3] = fmaf(A.w, B.w, ACC[3][3]);                               \
    } while (0)

// ---------------- edge kernel: one 64-edge tile per block iteration ----------------
__global__ void __launch_bounds__(256, 2)
    k_edge(const void* __restrict__ edges, const float* __restrict__ edge_attr,
           const float* __restrict__ ew1, const float* __restrict__ eb1,
           const float* __restrict__ ew2, const float* __restrict__ eb2,
           const float* __restrict__ cw1, const float* __restrict__ cb1,
           const float* __restrict__ cw2) {
    extern __shared__ float sm[];
    float* w1s = sm;                    // 131*64
    float* w2s = w1s + 131 * 64;        // 64*64
    float* w3s = w2s + 64 * 64;         // 64*64
    float* ins = w3s + 64 * 64;         // 131*STR (staging, reused for t1/ef)
    float* b1s = ins + 131 * STR;       // 64
    float* b2s = b1s + 64;
    float* b3s = b2s + 64;
    float* c2s = b3s + 64;
    float* gts = c2s + 64;              // 64
    float* cds = gts + 64;              // 3*TIL
    int* rs = (int*)(cds + 3 * TIL);    // 64
    int* cs = rs + 64;                  // 64

    const int tid = threadIdx.x;
    const int fc = tid & 15;   // feature quad 0..15
    const int er = tid >> 4;   // edge quad 0..15

    for (int i = tid; i < 131 * 64; i += 256) w1s[i] = ew1[i];
    for (int i = tid; i < 64 * 64; i += 256) {
        w2s[i] = ew2[i];
        w3s[i] = cw1[i];
    }
    if (tid < 64) {
        b1s[tid] = eb1[tid];
        b2s[tid] = eb2[tid];
        b3s[tid] = cb1[tid];
        c2s[tid] = cw2[tid];
    }

    const int ntile = NE / TIL;
    for (int t = blockIdx.x; t < ntile; t += gridDim.x) {
        __syncthreads();
        long long e0 = (long long)t * TIL;
        if (tid < TIL) {
            rs[tid] = edge_idx(edges, e0 + tid);
            cs[tid] = edge_idx(edges, (long long)NE + e0 + tid);
        }
        __syncthreads();
        if (tid < TIL) {
            int r = rs[tid], c = cs[tid];
            float dx = g_x[r * 3] - g_x[c * 3];
            float dy = g_x[r * 3 + 1] - g_x[c * 3 + 1];
            float dz = g_x[r * 3 + 2] - g_x[c * 3 + 2];
            cds[tid] = dx;
            cds[TIL + tid] = dy;
            cds[2 * TIL + tid] = dz;
            ins[128 * STR + tid] = dx * dx + dy * dy + dz * dz;
            ins[129 * STR + tid] = edge_attr[(e0 + tid) * 2];
            ins[130 * STR + tid] = edge_attr[(e0 + tid) * 2 + 1];
        }
        // gather h[row], h[col] -> transposed staging ins[k][e]
        for (int i = tid; i < TIL * 16; i += 256) {
            int e = i >> 4, kq = i & 15;
            float4 hv = *(const float4*)&g_h[rs[e] * HD + kq * 4];
            ins[(4 * kq + 0) * STR + e] = hv.x;
            ins[(4 * kq + 1) * STR + e] = hv.y;
            ins[(4 * kq + 2) * STR + e] = hv.z;
            ins[(4 * kq + 3) * STR + e] = hv.w;
            float4 hc = *(const float4*)&g_h[cs[e] * HD + kq * 4];
            ins[(64 + 4 * kq + 0) * STR + e] = hc.x;
            ins[(64 + 4 * kq + 1) * STR + e] = hc.y;
            ins[(64 + 4 * kq + 2) * STR + e] = hc.z;
            ins[(64 + 4 * kq + 3) * STR + e] = hc.w;
        }
        __syncthreads();

        float acc[4][4];
        // ---- GEMM1: [64,131]@[131,64] + b1, silu ----
#pragma unroll
        for (int i = 0; i < 4; i++)
#pragma unroll
            for (int j = 0; j < 4; j++) acc[i][j] = b1s[4 * fc + j];
#pragma unroll 4
        for (int k = 0; k < 131; k++) {
            float4 a = *(const float4*)&ins[k * STR + 4 * er];
            float4 b = *(const float4*)&w1s[k * 64 + 4 * fc];
            FMA16(acc, a, b);
        }
        __syncthreads();
#pragma unroll
        for (int i = 0; i < 4; i++)
#pragma unroll
            for (int j = 0; j < 4; j++)
                ins[(4 * fc + j) * STR + 4 * er + i] = silu_f(acc[i][j]);
        __syncthreads();

        // ---- GEMM2: t1@[64,64] + b2, silu -> ef ----
#pragma unroll
        for (int i = 0; i < 4; i++)
#pragma unroll
            for (int j = 0; j < 4; j++) acc[i][j] = b2s[4 * fc + j];
#pragma unroll 4
        for (int k = 0; k < 64; k++) {
            float4 a = *(const float4*)&ins[k * STR + 4 * er];
            float4 b = *(const float4*)&w2s[k * 64 + 4 * fc];
            FMA16(acc, a, b);
        }
        __syncthreads();
#pragma unroll
        for (int i = 0; i < 4; i++)
#pragma unroll
            for (int j = 0; j < 4; j++)
                ins[(4 * fc + j) * STR + 4 * er + i] = silu_f(acc[i][j]);
        __syncthreads();

        // ---- GEMM3: ef@coord_w1 + b3, silu, dot coord_w2 -> gate ----
#pragma unroll
        for (int i = 0; i < 4; i++)
#pragma unroll
            for (int j = 0; j < 4; j++) acc[i][j] = b3s[4 * fc + j];
#pragma unroll 4
        for (int k = 0; k < 64; k++) {
            float4 a = *(const float4*)&ins[k * STR + 4 * er];
            float4 b = *(const float4*)&w3s[k * 64 + 4 * fc];
            FMA16(acc, a, b);
        }
        float pr[4];
#pragma unroll
        for (int i = 0; i < 4; i++) {
            float p = 0.f;
#pragma unroll
            for (int j = 0; j < 4; j++) p = fmaf(silu_f(acc[i][j]), c2s[4 * fc + j], p);
            pr[i] = p;
        }
#pragma unroll
        for (int off = 8; off >= 1; off >>= 1)
#pragma unroll
            for (int i = 0; i < 4; i++)
                pr[i] += __shfl_xor_sync(0xffffffffu, pr[i], off);
        if (fc == 0)
#pragma unroll
            for (int i = 0; i < 4; i++) gts[4 * er + i] = pr[i];
        __syncthreads();

        // ---- scatter: agg += ef, acc3 += cd*gate, cnt += 1 ----
        {
            int e = tid & 63, fb = tid >> 6;
            int r = rs[e];
#pragma unroll
            for (int q = 0; q < 16; q++) {
                int f = fb * 16 + q;
                atomicAdd(&g_agg[r * HD + f], ins[f * STR + e]);
            }
            if (fb == 0) {
                float g = gts[e];
                atomicAdd(&g_acc3[r * 3 + 0], cds[e] * g);
                atomicAdd(&g_acc3[r * 3 + 1], cds[TIL + e] * g);
                atomicAdd(&g_acc3[r * 3 + 2], cds[2 * TIL + e] * g);
                atomicAdd(&g_cnt[r], 1.0f);
            }
        }
    }
}

// ---------------- node kernel: phi MLP, node MLP, state updates ----------------
__global__ void __launch_bounds__(256, 2)
    k_node(const float* __restrict__ nw1, const float* __restrict__ nb1,
           const float* __restrict__ nw2, const float* __restrict__ nb2,
           const float* __restrict__ vw1, const float* __restrict__ vb1,
           const float* __restrict__ vw2, const float* __restrict__ vb2) {
    extern __shared__ float sm[];
    float* wn1 = sm;                 // 128*64
    float* wn2 = wn1 + 128 * 64;     // 64*64
    float* wv1 = wn2 + 64 * 64;      // 64*64
    float* us = wv1 + 64 * 64;       // 128*STR
    float* nb1s = us + 128 * STR;    // 64
    float* nb2s = nb1s + 64;
    float* vb1s = nb2s + 64;
    float* vw2s = vb1s + 64;
    float* phis = vw2s + 64;         // 64

    const int tid = threadIdx.x;
    const int fc = tid & 15;
    const int er = tid >> 4;

    for (int i = tid; i < 128 * 64; i += 256) wn1[i] = nw1[i];
    for (int i = tid; i < 64 * 64; i += 256) {
        wn2[i] = nw2[i];
        wv1[i] = vw1[i];
    }
    if (tid < 64) {
        nb1s[tid] = nb1[tid];
        nb2s[tid] = nb2[tid];
        vb1s[tid] = vb1[tid];
        vw2s[tid] = vw2[tid];
    }
    const float vb2v = vb2[0];

    const int ntile = (NN + TIL - 1) / TIL;
    for (int t = blockIdx.x; t < ntile; t += gridDim.x) {
        __syncthreads();
        int n0 = t * TIL;
        for (int i = tid; i < TIL * 16; i += 256) {
            int nl = i >> 4, kq = i & 15;
            int n = n0 + nl;
            float4 hv = make_float4(0, 0, 0, 0), av = make_float4(0, 0, 0, 0);
            if (n < NN) {
                hv = *(const float4*)&g_h[n * 64 + kq * 4];
                av = *(const float4*)&g_agg[n * 64 + kq * 4];
            }
            us[(4 * kq + 0) * STR + nl] = hv.x;
            us[(4 * kq + 1) * STR + nl] = hv.y;
            us[(4 * kq + 2) * STR + nl] = hv.z;
            us[(4 * kq + 3) * STR + nl] = hv.w;
            us[(64 + 4 * kq + 0) * STR + nl] = av.x;
            us[(64 + 4 * kq + 1) * STR + nl] = av.y;
            us[(64 + 4 * kq + 2) * STR + nl] = av.z;
            us[(64 + 4 * kq + 3) * STR + nl] = av.w;
        }
        __syncthreads();

        float acc[4][4];
        // ---- vel path: silu(h@vw1+vb1) dot vw2 + vb2 -> phi ----
#pragma unroll
        for (int i = 0; i < 4; i++)
#pragma unroll
            for (int j = 0; j < 4; j++) acc[i][j] = vb1s[4 * fc + j];
#pragma unroll 4
        for (int k = 0; k < 64; k++) {
            float4 a = *(const float4*)&us[k * STR + 4 * er];
            float4 b = *(const float4*)&wv1[k * 64 + 4 * fc];
            FMA16(acc, a, b);
        }
        {
            float pr[4];
#pragma unroll
            for (int i = 0; i < 4; i++) {
                float p = 0.f;
#pragma unroll
                for (int j = 0; j < 4; j++) p = fmaf(silu_f(acc[i][j]), vw2s[4 * fc + j], p);
                pr[i] = p;
            }
#pragma unroll
            for (int off = 8; off >= 1; off >>= 1)
#pragma unroll
                for (int i = 0; i < 4; i++)
                    pr[i] += __shfl_xor_sync(0xffffffffu, pr[i], off);
            if (fc == 0)
#pragma unroll
                for (int i = 0; i < 4; i++) phis[4 * er + i] = pr[i] + vb2v;
        }

        // ---- node path GEMM1: [64,128]@[128,64] + nb1, silu ----
#pragma unroll
        for (int i = 0; i < 4; i++)
#pragma unroll
            for (int j = 0; j < 4; j++) acc[i][j] = nb1s[4 * fc + j];
#pragma unroll 4
        for (int k = 0; k < 128; k++) {
            float4 a = *(const float4*)&us[k * STR + 4 * er];
            float4 b = *(const float4*)&wn1[k * 64 + 4 * fc];
            FMA16(acc, a, b);
        }
        __syncthreads();
#pragma unroll
        for (int i = 0; i < 4; i++)
#pragma unroll
            for (int j = 0; j < 4; j++)
                us[(4 * fc + j) * STR + 4 * er + i] = silu_f(acc[i][j]);
        __syncthreads();

        // ---- node path GEMM2: s1@[64,64] + nb2 -> hn; h += hn ----
#pragma unroll
        for (int i = 0; i < 4; i++)
#pragma unroll
            for (int j = 0; j < 4; j++) acc[i][j] = nb2s[4 * fc + j];
#pragma unroll 4
        for (int k = 0; k < 64; k++) {
            float4 a = *(const float4*)&us[k * STR + 4 * er];
            float4 b = *(const float4*)&wn2[k * 64 + 4 * fc];
            FMA16(acc, a, b);
        }
#pragma unroll
        for (int i = 0; i < 4; i++) {
            int n = n0 + 4 * er + i;
            if (n < NN)
#pragma unroll
                for (int j = 0; j < 4; j++)
                    g_h[n * 64 + 4 * fc + j] += acc[i][j];
        }

        // ---- per-node coord/vel update + zero scratch ----
        if (tid < TIL) {
            int n = n0 + tid;
            if (n < NN) {
                float cnt = g_cnt[n];
                float inv = 1.0f / fmaxf(cnt, 1.0f);
                float phi = phis[tid];
#pragma unroll
                for (int d = 0; d < 3; d++) {
                    float a = g_acc3[n * 3 + d] * inv;
                    float vn = g_v[n * 3 + d] + a + phi * g_iv[n * 3 + d];
                    g_v[n * 3 + d] = vn;
                    g_x[n * 3 + d] += vn;
                    g_acc3[n * 3 + d] = 0.f;
                }
                g_cnt[n] = 0.f;
            }
        }
        for (int i = tid; i < TIL * 64; i += 256) {
            int n = n0 + (i >> 6);
            if (n < NN) g_agg[n * 64 + (i & 63)] = 0.f;
        }
    }
}

// ---------------- output: [x | h | v] ----------------
__global__ void k_copyout(float* __restrict__ out) {
    int i = blockIdx.x * blockDim.x + threadIdx.x;
    if (i < NN * 3) out[i] = g_x[i];
    if (i < NN * HD) out[NN * 3 + i] = g_h[i];
    if (i < NN * 3) out[NN * 3 + NN * HD + i] = g_v[i];
}

extern "C" void kernel_launch(void* const* d_in, const int* in_sizes, int n_in,
                              void* d_out, int out_size) {
    const float* his = (const float*)d_in[0];
    const float* loc = (const float*)d_in[1];
    const void* edges = d_in[2];
    const float* vel = (const float*)d_in[3];
    const float* eattr = (const float*)d_in[4];
    const float* emb_w = (const float*)d_in[5];
    const float* emb_b = (const float*)d_in[6];
    const float* ew1 = (const float*)d_in[7];
    const float* eb1 = (const float*)d_in[8];
    const float* ew2 = (const float*)d_in[9];
    const float* eb2 = (const float*)d_in[10];
    const float* nw1 = (const float*)d_in[11];
    const float* nb1 = (const float*)d_in[12];
    const float* nw2 = (const float*)d_in[13];
    const float* nb2 = (const float*)d_in[14];
    const float* cw1 = (const float*)d_in[15];
    const float* cb1 = (const float*)d_in[16];
    const float* cw2 = (const float*)d_in[17];
    const float* vw1 = (const float*)d_in[18];
    const float* vb1 = (const float*)d_in[19];
    const float* vw2 = (const float*)d_in[20];
    const float* vb2 = (const float*)d_in[21];

    size_t esm = (size_t)(131 * 64 + 2 * 64 * 64 + 131 * STR + 4 * 64 + 64 + 3 * TIL) * 4 +
                 2 * 64 * sizeof(int);
    size_t nsm = (size_t)(128 * 64 + 2 * 64 * 64 + 128 * STR + 5 * 64) * 4;
    cudaFuncSetAttribute(k_edge, cudaFuncAttributeMaxDynamicSharedMemorySize, (int)esm);
    cudaFuncSetAttribute(k_node, cudaFuncAttributeMaxDynamicSharedMemorySize, (int)nsm);

    k_detect<<<1, 1>>>(edges);
    k_init<<<(NN * HD + 255) / 256, 256>>>(his, loc, vel, emb_w, emb_b);
    for (int l = 0; l < NLAYERS; l++) {
        k_edge<<<304, 256, esm>>>(edges, eattr, ew1, eb1, ew2, eb2, cw1, cb1, cw2);
        k_node<<<157, 256, nsm>>>(nw1, nb1, nw2, nb2, vw1, vb1, vw2, vb2);
    }
    k_copyout<<<(NN * HD + 255) / 256, 256>>>((float*)d_out);
}

// round 3
// speedup vs baseline: 1.1133x; 1.1133x over previous
#include <cuda_runtime.h>

#define NN 10000
#define NE 320000
#define HD 64
#define NLAYERS 4
#define TE 128   // edges per tile (edge kernel)
#define TNN 64   // nodes per tile (node kernel)

typedef unsigned long long ull;

// ---------------- scratch state (allocation-free) ----------------
__device__ __align__(16) float g_h[NN * HD];
__device__ __align__(16) float g_agg[NN * HD];
__device__ float g_x[NN * 3];
__device__ float g_v[NN * 3];
__device__ float g_iv[NN * 3];
__device__ float g_acc3[NN * 3];
__device__ float g_cnt[NN];
__device__ int g_edge64;

__device__ __forceinline__ float silu_f(float x) {
    return __fdividef(x, 1.0f + __expf(-x));
}

// packed f32x2 helpers (FFMA2 path — ptxas never emits these from C++)
__device__ __forceinline__ ull d2(float x) {
    ull r;
    unsigned u = __float_as_uint(x);
    asm("mov.b64 %0, {%1, %1};" : "=l"(r) : "r"(u));
    return r;
}
__device__ __forceinline__ ull ffma2(ull a, ull b, ull c) {
    ull d;
    asm("fma.rn.f32x2 %0, %1, %2, %3;" : "=l"(d) : "l"(a), "l"(b), "l"(c));
    return d;
}
__device__ __forceinline__ float2 u2f(ull v) {
    unsigned lo, hi;
    asm("mov.b64 {%0, %1}, %2;" : "=r"(lo), "=r"(hi) : "l"(v));
    return make_float2(__uint_as_float(lo), __uint_as_float(hi));
}

// swizzled staging index: 16B-granule xor keeps transpose stores AND
// f-major epilogue stores conflict-free while a-loads stay LDS.128.
__device__ __forceinline__ int sidx(int k, int e, int RW) {
    return k * RW + ((((e >> 2) ^ ((k >> 2) & 7)) << 2) | (e & 3));
}

__device__ __forceinline__ int edge_idx(const void* edges, long long i) {
    if (g_edge64) return (int)((const long long*)edges)[i];
    return ((const int*)edges)[i];
}

__global__ void k_detect(const void* edges) {
    const int* p = (const int*)edges;
    int is64 = 1;
    for (int i = 1; i < 64; i += 2)
        if (p[i] != 0) is64 = 0;
    g_edge64 = is64;
}

__global__ void k_init(const float* __restrict__ his, const float* __restrict__ loc,
                       const float* __restrict__ vel, const float* __restrict__ emb_w,
                       const float* __restrict__ emb_b) {
    int idx = blockIdx.x * blockDim.x + threadIdx.x;
    if (idx < NN * HD) {
        int n = idx >> 6, j = idx & 63;
        float a = emb_b[j];
#pragma unroll
        for (int i = 0; i < 4; i++) a = fmaf(his[n * 4 + i], emb_w[i * 64 + j], a);
        g_h[idx] = a;
        g_agg[idx] = 0.f;
    }
    if (idx < NN * 3) {
        g_x[idx] = loc[idx];
        g_v[idx] = vel[idx];
        g_acc3[idx] = 0.f;
    }
    if (idx < NN) {
        float vx = vel[idx * 3], vy = vel[idx * 3 + 1], vz = vel[idx * 3 + 2];
        float inv = 1.0f / (sqrtf(vx * vx + vy * vy + vz * vz) + 1e-8f);
        g_iv[idx * 3] = vx * inv;
        g_iv[idx * 3 + 1] = vy * inv;
        g_iv[idx * 3 + 2] = vz * inv;
        g_cnt[idx] = 0.f;
    }
}

// ---- FFMA2 GEMM micro-kernel: per-thread 8 rows (edge pairs) x 4 cols ----
template <int RW>
__device__ __forceinline__ void gemm_t(const float* __restrict__ st,
                                       const float* __restrict__ w,
                                       const float* __restrict__ bias,
                                       ull (&acc)[4][4], int fc, int er, int K) {
#pragma unroll
    for (int j = 0; j < 4; j++) {
        ull bb = d2(bias[4 * fc + j]);
#pragma unroll
        for (int p = 0; p < 4; p++) acc[p][j] = bb;
    }
    const int eg0 = 2 * er, eg1 = 2 * er + 1;
    const int Km = K & ~3;
#pragma unroll 2
    for (int k0 = 0; k0 < Km; k0 += 4) {
        int s = (k0 >> 2) & 7;
        int o0 = ((eg0 ^ s) << 2), o1 = ((eg1 ^ s) << 2);
#pragma unroll
        for (int kk = 0; kk < 4; kk++) {
            const float* rp = st + (k0 + kk) * RW;
            ulonglong2 aA = *(const ulonglong2*)(rp + o0);
            ulonglong2 aB = *(const ulonglong2*)(rp + o1);
            float4 wv = *(const float4*)(w + (k0 + kk) * 64 + 4 * fc);
            ull b0 = d2(wv.x), b1 = d2(wv.y), b2 = d2(wv.z), b3 = d2(wv.w);
            acc[0][0] = ffma2(aA.x, b0, acc[0][0]);
            acc[1][0] = ffma2(aA.y, b0, acc[1][0]);
            acc[2][0] = ffma2(aB.x, b0, acc[2][0]);
            acc[3][0] = ffma2(aB.y, b0, acc[3][0]);
            acc[0][1] = ffma2(aA.x, b1, acc[0][1]);
            acc[1][1] = ffma2(aA.y, b1, acc[1][1]);
            acc[2][1] = ffma2(aB.x, b1, acc[2][1]);
            acc[3][1] = ffma2(aB.y, b1, acc[3][1]);
            acc[0][2] = ffma2(aA.x, b2, acc[0][2]);
            acc[1][2] = ffma2(aA.y, b2, acc[1][2]);
            acc[2][2] = ffma2(aB.x, b2, acc[2][2]);
            acc[3][2] = ffma2(aB.y, b2, acc[3][2]);
            acc[0][3] = ffma2(aA.x, b3, acc[0][3]);
            acc[1][3] = ffma2(aA.y, b3, acc[1][3]);
            acc[2][3] = ffma2(aB.x, b3, acc[2][3]);
            acc[3][3] = ffma2(aB.y, b3, acc[3][3]);
        }
    }
    for (int k = Km; k < K; k++) {
        int s = (k >> 2) & 7;
        const float* rp = st + k * RW;
        ulonglong2 aA = *(const ulonglong2*)(rp + ((eg0 ^ s) << 2));
        ulonglong2 aB = *(const ulonglong2*)(rp + ((eg1 ^ s) << 2));
        float4 wv = *(const float4*)(w + k * 64 + 4 * fc);
        ull b0 = d2(wv.x), b1 = d2(wv.y), b2 = d2(wv.z), b3 = d2(wv.w);
        acc[0][0] = ffma2(aA.x, b0, acc[0][0]);
        acc[1][0] = ffma2(aA.y, b0, acc[1][0]);
        acc[2][0] = ffma2(aB.x, b0, acc[2][0]);
        acc[3][0] = ffma2(aB.y, b0, acc[3][0]);
        acc[0][1] = ffma2(aA.x, b1, acc[0][1]);
        acc[1][1] = ffma2(aA.y, b1, acc[1][1]);
        acc[2][1] = ffma2(aB.x, b1, acc[2][1]);
        acc[3][1] = ffma2(aB.y, b1, acc[3][1]);
        acc[0][2] = ffma2(aA.x, b2, acc[0][2]);
        acc[1][2] = ffma2(aA.y, b2, acc[1][2]);
        acc[2][2] = ffma2(aB.x, b2, acc[2][2]);
        acc[3][2] = ffma2(aB.y, b2, acc[3][2]);
        acc[0][3] = ffma2(aA.x, b3, acc[0][3]);
        acc[1][3] = ffma2(aA.y, b3, acc[1][3]);
        acc[2][3] = ffma2(aB.x, b3, acc[2][3]);
        acc[3][3] = ffma2(aB.y, b3, acc[3][3]);
    }
}

// silu + transposed (feature-major, swizzled) store of the 8x4 tile
template <int RW>
__device__ __forceinline__ void store_silu_t(float* st, ull (&acc)[4][4], int fc, int er) {
    int s = fc & 7;
    int o0 = (((2 * er) ^ s) << 2), o1 = (((2 * er + 1) ^ s) << 2);
#pragma unroll
    for (int j = 0; j < 4; j++) {
        int r = 4 * fc + j;
        float2 f0 = u2f(acc[0][j]), f1 = u2f(acc[1][j]);
        float2 f2 = u2f(acc[2][j]), f3 = u2f(acc[3][j]);
        float4 v0 = make_float4(silu_f(f0.x), silu_f(f0.y), silu_f(f1.x), silu_f(f1.y));
        float4 v1 = make_float4(silu_f(f2.x), silu_f(f2.y), silu_f(f3.x), silu_f(f3.y));
        *(float4*)(st + r * RW + o0) = v0;
        *(float4*)(st + r * RW + o1) = v1;
    }
}

// ---------------- edge kernel: 128-edge tiles ----------------
__global__ void __launch_bounds__(256, 1)
    k_edge(const void* __restrict__ edges, const float* __restrict__ edge_attr,
           const float* __restrict__ ew1, const float* __restrict__ eb1,
           const float* __restrict__ ew2, const float* __restrict__ eb2,
           const float* __restrict__ cw1, const float* __restrict__ cb1,
           const float* __restrict__ cw2) {
    extern __shared__ float sm[];
    float* w1s = sm;                    // 131*64 = 8384
    float* w2s = w1s + 8384;            // 4096
    float* w3s = w2s + 4096;            // 4096
    float* ins = w3s + 4096;            // 131*128 = 16768 (swizzled staging)
    float* b1s = ins + 16768;           // 64
    float* b2s = b1s + 64;
    float* b3s = b2s + 64;
    float* c2s = b3s + 64;
    float* gts = c2s + 64;              // 128
    float* cds = gts + 128;             // 3*128
    int* rs = (int*)(cds + 384);        // 128
    int* cs = rs + 128;                 // 128

    const int tid = threadIdx.x;
    const int fc = tid & 15;   // feature quad 0..15
    const int er = tid >> 4;   // edge octet 0..15

    for (int i = tid; i < 2096; i += 256) ((float4*)w1s)[i] = ((const float4*)ew1)[i];
    for (int i = tid; i < 1024; i += 256) {
        ((float4*)w2s)[i] = ((const float4*)ew2)[i];
        ((float4*)w3s)[i] = ((const float4*)cw1)[i];
    }
    if (tid < 64) {
        b1s[tid] = eb1[tid];
        b2s[tid] = eb2[tid];
        b3s[tid] = cb1[tid];
        c2s[tid] = cw2[tid];
    }

    const int e = tid & 127;
    const int half = tid >> 7;
    const int ntile = NE / TE;
    for (int t = blockIdx.x; t < ntile; t += gridDim.x) {
        __syncthreads();
        long long e0 = (long long)t * TE;
        if (tid < TE) {
            rs[tid] = edge_idx(edges, e0 + tid);
            cs[tid] = edge_idx(edges, (long long)NE + e0 + tid);
        }
        __syncthreads();
        if (tid < TE) {
            int r = rs[e], c = cs[e];
            float dx = g_x[r * 3] - g_x[c * 3];
            float dy = g_x[r * 3 + 1] - g_x[c * 3 + 1];
            float dz = g_x[r * 3 + 2] - g_x[c * 3 + 2];
            cds[e] = dx;
            cds[128 + e] = dy;
            cds[256 + e] = dz;
            ins[sidx(128, e, 128)] = dx * dx + dy * dy + dz * dz;
            float2 ea = *(const float2*)&edge_attr[(e0 + e) * 2];
            ins[sidx(129, e, 128)] = ea.x;
            ins[sidx(130, e, 128)] = ea.y;
        }
        {
            int r = rs[e], c = cs[e];
#pragma unroll
            for (int q = 0; q < 8; q++) {
                int kq = half * 8 + q;
                float4 hv = *(const float4*)&g_h[r * 64 + 4 * kq];
                ins[sidx(4 * kq + 0, e, 128)] = hv.x;
                ins[sidx(4 * kq + 1, e, 128)] = hv.y;
                ins[sidx(4 * kq + 2, e, 128)] = hv.z;
                ins[sidx(4 * kq + 3, e, 128)] = hv.w;
                float4 hc = *(const float4*)&g_h[c * 64 + 4 * kq];
                ins[sidx(64 + 4 * kq + 0, e, 128)] = hc.x;
                ins[sidx(64 + 4 * kq + 1, e, 128)] = hc.y;
                ins[sidx(64 + 4 * kq + 2, e, 128)] = hc.z;
                ins[sidx(64 + 4 * kq + 3, e, 128)] = hc.w;
            }
        }
        __syncthreads();

        ull acc[4][4];
        // GEMM1: [128e,131]@[131,64] + b1, silu
        gemm_t<128>(ins, w1s, b1s, acc, fc, er, 131);
        __syncthreads();
        store_silu_t<128>(ins, acc, fc, er);
        __syncthreads();

        // GEMM2: @[64,64] + b2, silu -> ef
        gemm_t<128>(ins, w2s, b2s, acc, fc, er, 64);
        __syncthreads();
        store_silu_t<128>(ins, acc, fc, er);
        __syncthreads();

        // GEMM3: ef@cw1 + b3, silu, dot cw2 -> gate
        gemm_t<128>(ins, w3s, b3s, acc, fc, er, 64);
        {
            float g[8] = {0.f, 0.f, 0.f, 0.f, 0.f, 0.f, 0.f, 0.f};
#pragma unroll
            for (int p = 0; p < 4; p++)
#pragma unroll
                for (int j = 0; j < 4; j++) {
                    float2 f = u2f(acc[p][j]);
                    float c = c2s[4 * fc + j];
                    g[2 * p] = fmaf(silu_f(f.x), c, g[2 * p]);
                    g[2 * p + 1] = fmaf(silu_f(f.y), c, g[2 * p + 1]);
                }
#pragma unroll
            for (int m = 1; m < 16; m <<= 1)
#pragma unroll
                for (int i = 0; i < 8; i++)
                    g[i] += __shfl_xor_sync(0xffffffffu, g[i], m);
            if (fc == 0)
#pragma unroll
                for (int i = 0; i < 8; i++) gts[8 * er + i] = g[i];
        }
        __syncthreads();

        // scatter: agg += ef, acc3 += cd*gate, cnt += 1
        {
            int r = rs[e];
#pragma unroll
            for (int q = 0; q < 32; q++) {
                int f = half * 32 + q;
                atomicAdd(&g_agg[r * 64 + f], ins[sidx(f, e, 128)]);
            }
            if (half == 0) {
                float gg = gts[e];
                atomicAdd(&g_acc3[r * 3 + 0], cds[e] * gg);
                atomicAdd(&g_acc3[r * 3 + 1], cds[128 + e] * gg);
                atomicAdd(&g_acc3[r * 3 + 2], cds[256 + e] * gg);
                atomicAdd(&g_cnt[r], 1.0f);
            }
        }
    }
}

// ---------------- node kernel: 64-node tiles, 128 threads ----------------
__global__ void __launch_bounds__(128, 2)
    k_node(const float* __restrict__ nw1, const float* __restrict__ nb1,
           const float* __restrict__ nw2, const float* __restrict__ nb2,
           const float* __restrict__ vw1, const float* __restrict__ vb1,
           const float* __restrict__ vw2, const float* __restrict__ vb2) {
    extern __shared__ float sm[];
    float* wn1 = sm;                // 8192
    float* wn2 = wn1 + 8192;        // 4096
    float* wv1 = wn2 + 4096;        // 4096
    float* us = wv1 + 4096;         // 128*64 = 8192 (swizzled)
    float* nb1s = us + 8192;        // 64
    float* nb2s = nb1s + 64;
    float* vb1s = nb2s + 64;
    float* vw2s = vb1s + 64;
    float* phis = vw2s + 64;        // 64

    const int tid = threadIdx.x;
    const int fc = tid & 15;
    const int er = tid >> 4;   // 0..7

    for (int i = tid; i < 2048; i += 128) ((float4*)wn1)[i] = ((const float4*)nw1)[i];
    for (int i = tid; i < 1024; i += 128) {
        ((float4*)wn2)[i] = ((const float4*)nw2)[i];
        ((float4*)wv1)[i] = ((const float4*)vw1)[i];
    }
    if (tid < 64) {
        nb1s[tid] = nb1[tid];
        nb2s[tid] = nb2[tid];
        vb1s[tid] = vb1[tid];
        vw2s[tid] = vw2[tid];
    }
    const float vb2v = vb2[0];

    const int e = tid & 63;
    const int half = tid >> 6;
    const int ntile = (NN + TNN - 1) / TNN;
    for (int t = blockIdx.x; t < ntile; t += gridDim.x) {
        __syncthreads();
        int n0 = t * TNN;
        int n = n0 + e;
#pragma unroll
        for (int q = 0; q < 8; q++) {
            int kq = half * 8 + q;
            float4 hv = make_float4(0, 0, 0, 0), av = make_float4(0, 0, 0, 0);
            if (n < NN) {
                hv = *(const float4*)&g_h[n * 64 + 4 * kq];
                av = *(const float4*)&g_agg[n * 64 + 4 * kq];
            }
            us[sidx(4 * kq + 0, e, 64)] = hv.x;
            us[sidx(4 * kq + 1, e, 64)] = hv.y;
            us[sidx(4 * kq + 2, e, 64)] = hv.z;
            us[sidx(4 * kq + 3, e, 64)] = hv.w;
            us[sidx(64 + 4 * kq + 0, e, 64)] = av.x;
            us[sidx(64 + 4 * kq + 1, e, 64)] = av.y;
            us[sidx(64 + 4 * kq + 2, e, 64)] = av.z;
            us[sidx(64 + 4 * kq + 3, e, 64)] = av.w;
        }
        __syncthreads();

        ull acc[4][4];
        // vel MLP: silu(h@vw1+vb1) dot vw2 + vb2 -> phi
        gemm_t<64>(us, wv1, vb1s, acc, fc, er, 64);
        {
            float g[8] = {0.f, 0.f, 0.f, 0.f, 0.f, 0.f, 0.f, 0.f};
#pragma unroll
            for (int p = 0; p < 4; p++)
#pragma unroll
                for (int j = 0; j < 4; j++) {
                    float2 f = u2f(acc[p][j]);
                    float c = vw2s[4 * fc + j];
                    g[2 * p] = fmaf(silu_f(f.x), c, g[2 * p]);
                    g[2 * p + 1] = fmaf(silu_f(f.y), c, g[2 * p + 1]);
                }
#pragma unroll
            for (int m = 1; m < 16; m <<= 1)
#pragma unroll
                for (int i = 0; i < 8; i++)
                    g[i] += __shfl_xor_sync(0xffffffffu, g[i], m);
            if (fc == 0)
#pragma unroll
                for (int i = 0; i < 8; i++) phis[8 * er + i] = g[i] + vb2v;
        }

        // node GEMM1: cat(h,agg)@nw1 + nb1, silu -> rows 64..127 (over agg)
        gemm_t<64>(us, wn1, nb1s, acc, fc, er, 128);
        __syncthreads();
        store_silu_t<64>(us + 64 * 64, acc, fc, er);
        __syncthreads();

        // node GEMM2 -> hn; h += hn
        gemm_t<64>(us + 64 * 64, wn2, nb2s, acc, fc, er, 64);
#pragma unroll
        for (int p = 0; p < 4; p++) {
            int nlo = n0 + 8 * er + 2 * p, nhi = nlo + 1;
#pragma unroll
            for (int j = 0; j < 4; j++) {
                float2 f = u2f(acc[p][j]);
                if (nlo < NN) g_h[nlo * 64 + 4 * fc + j] += f.x;
                if (nhi < NN) g_h[nhi * 64 + 4 * fc + j] += f.y;
            }
        }

        // per-node coord/vel update + zero scratch
        if (tid < TNN) {
            int nu = n0 + tid;
            if (nu < NN) {
                float cnt = g_cnt[nu];
                float inv = 1.0f / fmaxf(cnt, 1.0f);
                float phi = phis[tid];
#pragma unroll
                for (int d = 0; d < 3; d++) {
                    float a = g_acc3[nu * 3 + d] * inv;
                    float vn = g_v[nu * 3 + d] + a + phi * g_iv[nu * 3 + d];
                    g_v[nu * 3 + d] = vn;
                    g_x[nu * 3 + d] += vn;
                    g_acc3[nu * 3 + d] = 0.f;
                }
                g_cnt[nu] = 0.f;
            }
        }
        for (int i = tid; i < TNN * 64; i += 128) {
            int nz = n0 + (i >> 6);
            if (nz < NN) g_agg[nz * 64 + (i & 63)] = 0.f;
        }
    }
}

// ---------------- output: [x | h | v] ----------------
__global__ void k_copyout(float* __restrict__ out) {
    int i = blockIdx.x * blockDim.x + threadIdx.x;
    if (i < NN * 3) out[i] = g_x[i];
    if (i < NN * HD) out[NN * 3 + i] = g_h[i];
    if (i < NN * 3) out[NN * 3 + NN * HD + i] = g_v[i];
}

extern "C" void kernel_launch(void* const* d_in, const int* in_sizes, int n_in,
                              void* d_out, int out_size) {
    const float* his = (const float*)d_in[0];
    const float* loc = (const float*)d_in[1];
    const void* edges = d_in[2];
    const float* vel = (const float*)d_in[3];
    const float* eattr = (const float*)d_in[4];
    const float* emb_w = (const float*)d_in[5];
    const float* emb_b = (const float*)d_in[6];
    const float* ew1 = (const float*)d_in[7];
    const float* eb1 = (const float*)d_in[8];
    const float* ew2 = (const float*)d_in[9];
    const float* eb2 = (const float*)d_in[10];
    const float* nw1 = (const float*)d_in[11];
    const float* nb1 = (const float*)d_in[12];
    const float* nw2 = (const float*)d_in[13];
    const float* nb2 = (const float*)d_in[14];
    const float* cw1 = (const float*)d_in[15];
    const float* cb1 = (const float*)d_in[16];
    const float* cw2 = (const float*)d_in[17];
    const float* vw1 = (const float*)d_in[18];
    const float* vb1 = (const float*)d_in[19];
    const float* vw2 = (const float*)d_in[20];
    const float* vb2 = (const float*)d_in[21];

    size_t esm = (size_t)(8384 + 4096 + 4096 + 16768 + 4 * 64 + 128 + 384) * 4 +
                 256 * sizeof(int);
    size_t nsm = (size_t)(8192 + 4096 + 4096 + 8192 + 4 * 64 + 64) * 4;
    cudaFuncSetAttribute(k_edge, cudaFuncAttributeMaxDynamicSharedMemorySize, (int)esm);
    cudaFuncSetAttribute(k_node, cudaFuncAttributeMaxDynamicSharedMemorySize, (int)nsm);

    k_detect<<<1, 1>>>(edges);
    k_init<<<(NN * HD + 255) / 256, 256>>>(his, loc, vel, emb_w, emb_b);
    for (int l = 0; l < NLAYERS; l++) {
        k_edge<<<148, 256, esm>>>(edges, eattr, ew1, eb1, ew2, eb2, cw1, cb1, cw2);
        k_node<<<157, 128, nsm>>>(nw1, nb1, nw2, nb2, vw1, vb1, vw2, vb2);
    }
    k_copyout<<<(NN * HD + 255) / 256, 256>>>((float*)d_out);
}